// round 6
// baseline (speedup 1.0000x reference)
#include <cuda_runtime.h>

// Problem constants
#define Bn 2
#define Ln 16
#define Cn 16
#define Hn 64
#define Wn 64
#define HW (Hn * Wn)            // 4096

// Padded transposed image: entry = 16 channels (64B).
// Rows cover y = -1..65 (PR=67), cols cover x = -1..64 (PC=66).
// Border entries are never written -> stay zero (device globals zero-init).
#define PR 67
#define PC 66
#define PLANE (PR * PC)         // 4422 entries per (b,l)

__device__ float g_imgT[Bn * Ln * PLANE * Cn];   // ~9.06 MB

// ---------------------------------------------------------------------------
// Kernel 1: transpose images (B,L,C,H,W) -> padded (B,L,(H+3),(W+2),C).
// One thread per 4 adjacent pixels (same row): 16 float4 channel loads,
// 16 float4 stores (4 entries x 64B contiguous).
// ---------------------------------------------------------------------------
__global__ void __launch_bounds__(256) transpose_kernel(const float* __restrict__ images) {
    int t = blockIdx.x * blockDim.x + threadIdx.x;   // 0 .. B*L*HW/4-1
    if (t >= Bn * Ln * HW / 4) return;
    int q4 = t & (HW / 4 - 1);        // 4-pixel group within plane
    int bl = t >> 10;
    int hw = q4 << 2;
    int w = hw & (Wn - 1);            // w, w+1, w+2, w+3 all in same row
    int h = hw >> 6;

    const float4* src = reinterpret_cast<const float4*>(images + (size_t)bl * Cn * HW) + q4;
    float4 v[Cn];
#pragma unroll
    for (int c = 0; c < Cn; c++) v[c] = src[(size_t)c * (HW / 4)];

    float* base = g_imgT + ((size_t)bl * PLANE + (size_t)(h + 1) * PC + (w + 1)) * Cn;
    // pixel k (k=0..3) -> entry base + k*Cn; channels = component k of v[c]
    float4* d0 = reinterpret_cast<float4*>(base);
    float4* d1 = reinterpret_cast<float4*>(base + Cn);
    float4* d2 = reinterpret_cast<float4*>(base + 2 * Cn);
    float4* d3 = reinterpret_cast<float4*>(base + 3 * Cn);
#pragma unroll
    for (int q = 0; q < 4; q++) {
        d0[q] = make_float4(v[4*q+0].x, v[4*q+1].x, v[4*q+2].x, v[4*q+3].x);
        d1[q] = make_float4(v[4*q+0].y, v[4*q+1].y, v[4*q+2].y, v[4*q+3].y);
        d2[q] = make_float4(v[4*q+0].z, v[4*q+1].z, v[4*q+2].z, v[4*q+3].z);
        d3[q] = make_float4(v[4*q+0].w, v[4*q+1].w, v[4*q+2].w, v[4*q+3].w);
    }
}

// ---------------------------------------------------------------------------
// Kernel 2: main. Block = 256 threads = 128 adjacent pixels of one (b,i),
// 2 lanes/pixel, each lane owns 8 channels (2 float4 per corner).
// Phase 1: cooperative cumsum of flows into smem (17-padded, conflict-free).
// Phase 2: j-loop reads cum[j] from smem (no loop-carried load dependency),
// gathers 4 zero-padded corners, accumulates 8 channels.
// ---------------------------------------------------------------------------
__global__ void __launch_bounds__(256) gridsample_pscan_kernel(const float* __restrict__ flows,
                                                               float* __restrict__ out) {
    __shared__ float s_cum[2][128][17];   // [d][pixel][j], 17-padded

    const int tid  = threadIdx.x;
    const int bi   = blockIdx.x >> 5;           // 32 tiles per (b,i)
    const int tile = blockIdx.x & 31;
    const int i    = bi & (Ln - 1);
    const int b    = bi >> 4;
    const int hw0  = tile << 7;                  // 128 pixels per block

    // ---- Phase 1: cumsum over L for this block's 128 pixels ----
    {
        int d = tid >> 7;           // 0: x, 1: y
        int p = tid & 127;
        const float* f = flows + ((size_t)(b * Ln) * 2 + d) * HW + (hw0 + p);
        float acc = 0.0f;
#pragma unroll
        for (int j = 0; j < Ln; j++) {
            acc += f[(size_t)(j * 2) * HW];
            s_cum[d][p][j] = acc;
        }
    }
    __syncthreads();

    // ---- Phase 2: sample & accumulate ----
    const int cg = tid & 1;         // channel group: 8 channels
    const int p  = tid >> 1;        // pixel within block
    const int hw = hw0 + p;
    const int w  = hw & (Wn - 1);
    const int h  = hw >> 6;

    const float uxb = (float)w + 0.5f;   // x in "u" domain before wrap
    const float fyb = (float)h;

    const float cix = s_cum[0][p][i];
    const float ciy = s_cum[1][p][i];

    const float* imgb = g_imgT + (size_t)b * Ln * PLANE * Cn + cg * 8;

    float acc[8];
#pragma unroll
    for (int c = 0; c < 8; c++) acc[c] = 0.0f;

#pragma unroll 4
    for (int j = 0; j <= i; j++) {
        float relx = cix - s_cum[0][p][j];
        float rely = ciy - s_cum[1][p][j];

        // x: wrap into [0,64), then shift by -0.5
        float u  = fmaf(relx, 32.0f, uxb);
        float fq = floorf(u * 0.015625f);           // u/64
        float ix = fmaf(fq, -64.0f, u) - 0.5f;      // in [-0.5, 63.5)
        // y: clamp to [-1, 64] (equivalent to validity masking w/ zero border)
        float iy = fmaf(rely, 32.0f, fyb);
        iy = fminf(fmaxf(iy, -1.0f), 64.0f);

        float x0f = floorf(ix), y0f = floorf(iy);
        float wx = ix - x0f,    wy = iy - y0f;
        int x0 = (int)x0f, y0 = (int)y0f;           // x0 in [-1,63], y0 in [-1,64]

        float wx1 = 1.0f - wx, wy1 = 1.0f - wy;
        float w00 = wx1 * wy1, w01 = wx * wy1, w10 = wx1 * wy, w11 = wx * wy;

        // entry index: j*PLANE + (y0+1)*PC + (x0+1) -> always in-bounds
        int e = j * PLANE + y0 * PC + x0 + (PC + 1);
        const float* pp = imgb + ((size_t)e << 4);

        const float4 a00 = *reinterpret_cast<const float4*>(pp);
        const float4 b00 = *reinterpret_cast<const float4*>(pp + 4);
        const float4 a01 = *reinterpret_cast<const float4*>(pp + Cn);
        const float4 b01 = *reinterpret_cast<const float4*>(pp + Cn + 4);
        const float4 a10 = *reinterpret_cast<const float4*>(pp + PC * Cn);
        const float4 b10 = *reinterpret_cast<const float4*>(pp + PC * Cn + 4);
        const float4 a11 = *reinterpret_cast<const float4*>(pp + (PC + 1) * Cn);
        const float4 b11 = *reinterpret_cast<const float4*>(pp + (PC + 1) * Cn + 4);

        acc[0] += w00 * a00.x + w01 * a01.x + w10 * a10.x + w11 * a11.x;
        acc[1] += w00 * a00.y + w01 * a01.y + w10 * a10.y + w11 * a11.y;
        acc[2] += w00 * a00.z + w01 * a01.z + w10 * a10.z + w11 * a11.z;
        acc[3] += w00 * a00.w + w01 * a01.w + w10 * a10.w + w11 * a11.w;
        acc[4] += w00 * b00.x + w01 * b01.x + w10 * b10.x + w11 * b11.x;
        acc[5] += w00 * b00.y + w01 * b01.y + w10 * b10.y + w11 * b11.y;
        acc[6] += w00 * b00.z + w01 * b01.z + w10 * b10.z + w11 * b11.z;
        acc[7] += w00 * b00.w + w01 * b01.w + w10 * b10.w + w11 * b11.w;
    }

    // out[b,i,c,h,w]: this lane owns channels cg*8 .. cg*8+7
    float* op = out + (size_t)bi * Cn * HW + (size_t)(cg * 8) * HW + hw;
#pragma unroll
    for (int c = 0; c < 8; c++) op[(size_t)c * HW] = acc[c];
}

extern "C" void kernel_launch(void* const* d_in, const int* in_sizes, int n_in,
                              void* d_out, int out_size) {
    const float* flows  = (const float*)d_in[0];   // (B,L,2,H,W)
    const float* images = (const float*)d_in[1];   // (B,L,C,H,W)
    float* out = (float*)d_out;                    // (B,L,C,H,W)

    const int nT = Bn * Ln * HW / 4;       // 32768 transpose threads
    transpose_kernel<<<(nT + 255) / 256, 256>>>(images);

    gridsample_pscan_kernel<<<Bn * Ln * 32, 256>>>(flows, out);
}